// round 1
// baseline (speedup 1.0000x reference)
#include <cuda_runtime.h>

#define B_ 512
#define L_ 100
#define E_ 50
#define D_ 512
#define BLD ((size_t)B_ * L_ * D_)
#define NEGF -9000000000000000.0f

// ---- scratch (static device globals: allocation-free at runtime) ----
__device__ float g_X[(size_t)B_ * L_ * D_];      // gathered node feats (100 MB)
__device__ float g_EDGE[(size_t)B_ * E_ * D_];   // edge feats (50 MB)
__device__ float g_ATTE[(size_t)B_ * E_ * L_];   // att_edge
__device__ float g_ATTN[(size_t)B_ * L_ * E_];   // att_node
__device__ float g_S[B_ * L_];                   // leaky(c0 + x.w_an)
__device__ float g_U[B_ * L_];                   // x.w_a2n
__device__ float g_wan[D_], g_wa2n[D_], g_w3e[D_];
__device__ float g_c0;

__device__ __forceinline__ float leaky(float x) { return x >= 0.f ? x : 0.2f * x; }

// ---- K0: fold W2/W3 into vectors: w_an=W2@a[D:], w_a2n=W2@a2[:D], w3e=W3@a2[D:], c0=ctx.a[:D]
__global__ void k0(const float* __restrict__ W2, const float* __restrict__ W3,
                   const float* __restrict__ ctx, const float* __restrict__ a,
                   const float* __restrict__ a2) {
    int d = threadIdx.x;      // 512
    int which = blockIdx.x;   // 4 blocks
    if (which < 3) {
        const float* M = (which == 2) ? W3 : W2;
        const float* vec = (which == 0) ? (a + D_) : (which == 1 ? a2 : (a2 + D_));
        float s = 0.f;
        for (int j = 0; j < D_; j++) s += M[(size_t)d * D_ + j] * vec[j];
        if (which == 0) g_wan[d] = s;
        else if (which == 1) g_wa2n[d] = s;
        else g_w3e[d] = s;
    } else {
        __shared__ float sh[512];
        sh[d] = ctx[d] * a[d];
        __syncthreads();
        for (int o = 256; o > 0; o >>= 1) { if (d < o) sh[d] += sh[d + o]; __syncthreads(); }
        if (d == 0) g_c0 = sh[0];
    }
}

// ---- K1: gather x=emb1[inputs] -> g_X, nodes2=emb2[inputs] -> out section 3,
//          fused dots -> g_S (leaky(c0 + x.w_an)), g_U (x.w_a2n)
__global__ void k1(const int* __restrict__ inputs, const float* __restrict__ emb1,
                   const float* __restrict__ emb2, float* __restrict__ out3) {
    int bl = blockIdx.x;        // B*L
    int t = threadIdx.x;        // 128: one float4 per thread covers D=512
    size_t nid = (size_t)inputs[bl];
    const float4* r1 = (const float4*)(emb1 + nid * D_);
    const float4* r2 = (const float4*)(emb2 + nid * D_);
    float4* xo = (float4*)(g_X + (size_t)bl * D_);
    float4* o3 = (float4*)(out3 + (size_t)bl * D_);

    float4 v = r1[t];
    xo[t] = v;
    o3[t] = r2[t];
    float4 wa = ((const float4*)g_wan)[t];
    float4 wb = ((const float4*)g_wa2n)[t];
    float dan = v.x * wa.x + v.y * wa.y + v.z * wa.z + v.w * wa.w;
    float da2 = v.x * wb.x + v.y * wb.y + v.z * wb.z + v.w * wb.w;

    for (int off = 16; off; off >>= 1) {
        dan += __shfl_xor_sync(0xffffffffu, dan, off);
        da2 += __shfl_xor_sync(0xffffffffu, da2, off);
    }
    __shared__ float sA[4], sB[4];
    if ((t & 31) == 0) { sA[t >> 5] = dan; sB[t >> 5] = da2; }
    __syncthreads();
    if (t == 0) {
        float s = g_c0 + sA[0] + sA[1] + sA[2] + sA[3];
        g_S[bl] = leaky(s);
        g_U[bl] = sB[0] + sB[1] + sB[2] + sB[3];
    }
}

// ---- K2: att_edge[b,e,:] = softmax_l( mask ? s_node[b,l] : NEG )
__global__ void k2(const int* __restrict__ HT) {
    int b = blockIdx.x;
    __shared__ float s[L_];
    int t = threadIdx.x;   // 256 = 8 warps
    if (t < L_) s[t] = g_S[b * L_ + t];
    __syncthreads();
    int w = t >> 5, lane = t & 31;
    for (int e = w; e < E_; e += 8) {
        const int* m = HT + ((size_t)b * E_ + e) * L_;
        float vals[4];
        float mx = -3.4e38f;
        #pragma unroll
        for (int k = 0; k < 4; k++) {
            int l = lane + 32 * k;
            float v = -3.4e38f;
            if (l < L_) v = (m[l] > 0) ? s[l] : NEGF;
            vals[k] = v;
            mx = fmaxf(mx, v);
        }
        for (int off = 16; off; off >>= 1) mx = fmaxf(mx, __shfl_xor_sync(0xffffffffu, mx, off));
        float sum = 0.f;
        #pragma unroll
        for (int k = 0; k < 4; k++) {
            int l = lane + 32 * k;
            float ev = 0.f;
            if (l < L_) ev = expf(vals[k] - mx);
            vals[k] = ev;
            sum += ev;
        }
        for (int off = 16; off; off >>= 1) sum += __shfl_xor_sync(0xffffffffu, sum, off);
        float inv = 1.f / sum;
        float* o = g_ATTE + ((size_t)b * E_ + e) * L_;
        #pragma unroll
        for (int k = 0; k < 4; k++) { int l = lane + 32 * k; if (l < L_) o[l] = vals[k] * inv; }
    }
}

// ---- K3: edge[b,e,dtile] = sum_l att_edge[b,e,l] * x[b,l,dtile]   (grid: B x 8 tiles of 64)
__global__ void k3() {
    int b = blockIdx.x;
    int dt = blockIdx.y * 64;
    __shared__ float xs[L_][64];   // 25.6 KB
    __shared__ float aw[E_][L_];   // 20 KB
    int t = threadIdx.x;           // 256
    for (int idx = t; idx < L_ * 64; idx += 256) {
        int l = idx >> 6, j = idx & 63;
        xs[l][j] = g_X[((size_t)b * L_ + l) * D_ + dt + j];
    }
    for (int idx = t; idx < E_ * L_; idx += 256)
        aw[idx / L_][idx % L_] = g_ATTE[(size_t)b * E_ * L_ + idx];
    __syncthreads();

    int j = t & 63, g = t >> 6;   // 4 e-groups
    float acc[13];
    #pragma unroll
    for (int k = 0; k < 13; k++) acc[k] = 0.f;
    for (int l = 0; l < L_; l++) {
        float xv = xs[l][j];
        #pragma unroll
        for (int k = 0; k < 13; k++) {
            int e = g + 4 * k;
            if (e < E_) acc[k] += aw[e][l] * xv;
        }
    }
    #pragma unroll
    for (int k = 0; k < 13; k++) {
        int e = g + 4 * k;
        if (e < E_) g_EDGE[((size_t)b * E_ + e) * D_ + dt + j] = acc[k];
    }
}

// ---- K4: v[b,e] = edge.w3e; att_node[b,l,:] = softmax_e( mask ? leaky(u+v) : NEG )
__global__ void k4(const int* __restrict__ HT) {
    int b = blockIdx.x;
    int t = threadIdx.x;   // 128
    __shared__ float vsh[E_];
    __shared__ float ush[L_];
    int w = t >> 5, lane = t & 31;
    for (int e = w; e < E_; e += 4) {
        const float* er = g_EDGE + ((size_t)b * E_ + e) * D_;
        float d = 0.f;
        for (int i = lane; i < D_; i += 32) d += er[i] * g_w3e[i];
        for (int off = 16; off; off >>= 1) d += __shfl_xor_sync(0xffffffffu, d, off);
        if (lane == 0) vsh[e] = d;
    }
    if (t < L_) ush[t] = g_U[b * L_ + t];
    __syncthreads();

    if (t < L_) {
        int l = t;
        float u = ush[l];
        float vals[E_];
        float mx = -3.4e38f;
        #pragma unroll
        for (int e = 0; e < E_; e++) {
            float s2 = leaky(u + vsh[e]);
            float val = (HT[((size_t)b * E_ + e) * L_ + l] > 0) ? s2 : NEGF;
            vals[e] = val;
            mx = fmaxf(mx, val);
        }
        float sum = 0.f;
        #pragma unroll
        for (int e = 0; e < E_; e++) { vals[e] = expf(vals[e] - mx); sum += vals[e]; }
        float inv = 1.f / sum;
        float* o = g_ATTN + ((size_t)b * L_ + l) * E_;
        #pragma unroll
        for (int e = 0; e < E_; e++) o[e] = vals[e] * inv;
    }
}

// ---- K5: node[b,l,dtile] = sum_e att_node[b,l,e]*edge[b,e,dtile] + x; write out twice
__global__ void k5(float* __restrict__ out) {
    int b = blockIdx.x;
    int dt = blockIdx.y * 64;
    __shared__ float es[E_][64];   // 12.8 KB
    __shared__ float an[L_][E_];   // 20 KB
    int t = threadIdx.x;           // 256
    for (int idx = t; idx < E_ * 64; idx += 256) {
        int e = idx >> 6, j = idx & 63;
        es[e][j] = g_EDGE[((size_t)b * E_ + e) * D_ + dt + j];
    }
    for (int idx = t; idx < L_ * E_; idx += 256)
        an[idx / E_][idx % E_] = g_ATTN[(size_t)b * L_ * E_ + idx];
    __syncthreads();

    int j = t & 63, g = t >> 6;    // 4 l-groups, l = g + 4k covers 0..99
    float acc[25];
    #pragma unroll
    for (int k = 0; k < 25; k++) acc[k] = 0.f;
    for (int e = 0; e < E_; e++) {
        float ev = es[e][j];
        #pragma unroll
        for (int k = 0; k < 25; k++) {
            int l = g + 4 * k;
            acc[k] += an[l][e] * ev;
        }
    }
    #pragma unroll
    for (int k = 0; k < 25; k++) {
        int l = g + 4 * k;
        size_t off = ((size_t)b * L_ + l) * D_ + dt + j;
        float val = acc[k] + g_X[off];
        out[off] = val;
        out[BLD + off] = val;
    }
}

extern "C" void kernel_launch(void* const* d_in, const int* in_sizes, int n_in,
                              void* d_out, int out_size) {
    const int*   inputs = (const int*)d_in[0];
    const int*   HT     = (const int*)d_in[1];
    // d_in[2]=G, d_in[3]=EG unused
    const float* emb1   = (const float*)d_in[4];
    const float* emb2   = (const float*)d_in[5];
    const float* W2     = (const float*)d_in[6];
    const float* W3     = (const float*)d_in[7];
    const float* ctx    = (const float*)d_in[8];
    const float* a      = (const float*)d_in[9];
    const float* a2     = (const float*)d_in[10];
    float* out = (float*)d_out;

    k0<<<4, 512>>>(W2, W3, ctx, a, a2);
    k1<<<B_ * L_, 128>>>(inputs, emb1, emb2, out + 2 * BLD);
    k2<<<B_, 256>>>(HT);
    k3<<<dim3(B_, 8), 256>>>();
    k4<<<B_, 128>>>(HT);
    k5<<<dim3(B_, 8), 256>>>(out);
}

// round 2
// speedup vs baseline: 1.0098x; 1.0098x over previous
#include <cuda_runtime.h>

#define B_ 512
#define L_ 100
#define E_ 50
#define D_ 512
#define DT 128
#define BLD ((size_t)B_ * L_ * D_)
#define NEGF -9000000000000000.0f

// ---- scratch (static device globals: allocation-free at runtime) ----
__device__ float g_X[(size_t)B_ * L_ * D_];      // gathered node feats (100 MB)
__device__ float g_EDGE[(size_t)B_ * E_ * D_];   // edge feats (50 MB)
__device__ float g_ATTE[(size_t)B_ * E_ * L_];   // att_edge  [B][E][L]
__device__ float g_ATTN[(size_t)B_ * L_ * E_];   // att_node  [B][L][E]
__device__ float g_S[B_ * L_];                   // leaky(c0 + x.w_an)
__device__ float g_U[B_ * L_];                   // x.w_a2n
__device__ float g_wan[D_], g_wa2n[D_], g_w3e[D_];
__device__ float g_c0;

__device__ __forceinline__ float leaky(float x) { return x >= 0.f ? x : 0.2f * x; }

__device__ __forceinline__ unsigned long long fma2(unsigned long long a,
                                                   unsigned long long b,
                                                   unsigned long long c) {
    unsigned long long d;
    asm("fma.rn.f32x2 %0, %1, %2, %3;" : "=l"(d) : "l"(a), "l"(b), "l"(c));
    return d;
}

// ---- K0: fold W2/W3 into vectors
__global__ void k0(const float* __restrict__ W2, const float* __restrict__ W3,
                   const float* __restrict__ ctx, const float* __restrict__ a,
                   const float* __restrict__ a2) {
    int d = threadIdx.x;      // 512
    int which = blockIdx.x;   // 4
    if (which < 3) {
        const float* M = (which == 2) ? W3 : W2;
        const float* vec = (which == 0) ? (a + D_) : (which == 1 ? a2 : (a2 + D_));
        float s = 0.f;
        for (int j = 0; j < D_; j++) s += M[(size_t)d * D_ + j] * vec[j];
        if (which == 0) g_wan[d] = s;
        else if (which == 1) g_wa2n[d] = s;
        else g_w3e[d] = s;
    } else {
        __shared__ float sh[512];
        sh[d] = ctx[d] * a[d];
        __syncthreads();
        for (int o = 256; o > 0; o >>= 1) { if (d < o) sh[d] += sh[d + o]; __syncthreads(); }
        if (d == 0) g_c0 = sh[0];
    }
}

// ---- K1: gather + fused dots
__global__ void k1(const int* __restrict__ inputs, const float* __restrict__ emb1,
                   const float* __restrict__ emb2, float* __restrict__ out3) {
    int bl = blockIdx.x;        // B*L
    int t = threadIdx.x;        // 128
    size_t nid = (size_t)inputs[bl];
    const float4* r1 = (const float4*)(emb1 + nid * D_);
    const float4* r2 = (const float4*)(emb2 + nid * D_);
    float4* xo = (float4*)(g_X + (size_t)bl * D_);
    float4* o3 = (float4*)(out3 + (size_t)bl * D_);

    float4 v = r1[t];
    xo[t] = v;
    o3[t] = r2[t];
    float4 wa = ((const float4*)g_wan)[t];
    float4 wb = ((const float4*)g_wa2n)[t];
    float dan = v.x * wa.x + v.y * wa.y + v.z * wa.z + v.w * wa.w;
    float da2 = v.x * wb.x + v.y * wb.y + v.z * wb.z + v.w * wb.w;

    for (int off = 16; off; off >>= 1) {
        dan += __shfl_xor_sync(0xffffffffu, dan, off);
        da2 += __shfl_xor_sync(0xffffffffu, da2, off);
    }
    __shared__ float sA[4], sB[4];
    if ((t & 31) == 0) { sA[t >> 5] = dan; sB[t >> 5] = da2; }
    __syncthreads();
    if (t == 0) {
        float s = g_c0 + sA[0] + sA[1] + sA[2] + sA[3];
        g_S[bl] = leaky(s);
        g_U[bl] = sB[0] + sB[1] + sB[2] + sB[3];
    }
}

// ---- K2: att_edge[b,e,:] = softmax_l( mask ? s_node[b,l] : NEG )
__global__ void k2(const int* __restrict__ HT) {
    int b = blockIdx.x;
    __shared__ float s[L_];
    int t = threadIdx.x;   // 256
    if (t < L_) s[t] = g_S[b * L_ + t];
    __syncthreads();
    int w = t >> 5, lane = t & 31;
    for (int e = w; e < E_; e += 8) {
        const int* m = HT + ((size_t)b * E_ + e) * L_;
        float vals[4];
        float mx = -3.4e38f;
        #pragma unroll
        for (int k = 0; k < 4; k++) {
            int l = lane + 32 * k;
            float v = -3.4e38f;
            if (l < L_) v = (m[l] > 0) ? s[l] : NEGF;
            vals[k] = v;
            mx = fmaxf(mx, v);
        }
        for (int off = 16; off; off >>= 1) mx = fmaxf(mx, __shfl_xor_sync(0xffffffffu, mx, off));
        float sum = 0.f;
        #pragma unroll
        for (int k = 0; k < 4; k++) {
            int l = lane + 32 * k;
            float ev = 0.f;
            if (l < L_) ev = expf(vals[k] - mx);
            vals[k] = ev;
            sum += ev;
        }
        for (int off = 16; off; off >>= 1) sum += __shfl_xor_sync(0xffffffffu, sum, off);
        float inv = 1.f / sum;
        float* o = g_ATTE + ((size_t)b * E_ + e) * L_;
        #pragma unroll
        for (int k = 0; k < 4; k++) { int l = lane + 32 * k; if (l < L_) o[l] = vals[k] * inv; }
    }
}

// ---- K3: edge[b,e,dtile] = sum_l att_edge[b,e,l] * x[b,l,dtile]
//      grid (B, 4), block 256. Register tile: 7e x 4j per thread, f32x2 FMA.
__global__ void __launch_bounds__(256, 2) k3() {
    int b = blockIdx.x;
    int dt = blockIdx.y * DT;
    __shared__ float xs[L_][DT];            // 51.2 KB
    __shared__ float2 aw2[L_][E_ + 2];      // duplicated weights, 41.6 KB
    int t = threadIdx.x;

    for (int idx = t; idx < L_ * (DT / 4); idx += 256) {
        int l = idx >> 5, q = idx & 31;
        ((float4*)xs[l])[q] = *(const float4*)(g_X + ((size_t)b * L_ + l) * D_ + dt + q * 4);
    }
    for (int idx = t; idx < E_ * L_; idx += 256) {
        int e = idx / L_, l = idx % L_;
        float v = g_ATTE[(size_t)b * E_ * L_ + idx];
        aw2[l][e] = make_float2(v, v);
    }
    __syncthreads();

    int eg = t & 7, jg = t >> 3;
    int j0 = jg * 4;
    unsigned long long acc[7][2];
    #pragma unroll
    for (int k = 0; k < 7; k++) { acc[k][0] = 0ULL; acc[k][1] = 0ULL; }

    for (int l = 0; l < L_; l++) {
        ulonglong2 xv = *(const ulonglong2*)&xs[l][j0];
        #pragma unroll
        for (int k = 0; k < 7; k++) {
            int e = eg + 8 * k;
            if (e < E_) {
                unsigned long long aa = *(const unsigned long long*)&aw2[l][e];
                acc[k][0] = fma2(aa, xv.x, acc[k][0]);
                acc[k][1] = fma2(aa, xv.y, acc[k][1]);
            }
        }
    }
    #pragma unroll
    for (int k = 0; k < 7; k++) {
        int e = eg + 8 * k;
        if (e < E_) {
            float2 lo = *(float2*)&acc[k][0];
            float2 hi = *(float2*)&acc[k][1];
            float4 o = make_float4(lo.x, lo.y, hi.x, hi.y);
            *(float4*)(g_EDGE + ((size_t)b * E_ + e) * D_ + dt + j0) = o;
        }
    }
}

// ---- K4: v[b,e] = edge.w3e; att_node softmax over e
__global__ void k4(const int* __restrict__ HT) {
    int b = blockIdx.x;
    int t = threadIdx.x;   // 256
    __shared__ float vsh[E_];
    __shared__ float ush[L_];
    __shared__ float4 wsh[D_ / 4];
    int w = t >> 5, lane = t & 31;
    for (int i = t; i < D_ / 4; i += 256) wsh[i] = ((const float4*)g_w3e)[i];
    if (t < L_) ush[t] = g_U[b * L_ + t];
    __syncthreads();
    for (int e = w; e < E_; e += 8) {
        const float4* er = (const float4*)(g_EDGE + ((size_t)b * E_ + e) * D_);
        float d = 0.f;
        #pragma unroll
        for (int i = 0; i < 4; i++) {
            float4 ev = er[lane + 32 * i];
            float4 wv = wsh[lane + 32 * i];
            d += ev.x * wv.x + ev.y * wv.y + ev.z * wv.z + ev.w * wv.w;
        }
        for (int off = 16; off; off >>= 1) d += __shfl_xor_sync(0xffffffffu, d, off);
        if (lane == 0) vsh[e] = d;
    }
    __syncthreads();

    if (t < L_) {
        int l = t;
        float u = ush[l];
        float vals[E_];
        float mx = -3.4e38f;
        #pragma unroll
        for (int e = 0; e < E_; e++) {
            float s2 = leaky(u + vsh[e]);
            float val = (HT[((size_t)b * E_ + e) * L_ + l] > 0) ? s2 : NEGF;
            vals[e] = val;
            mx = fmaxf(mx, val);
        }
        float sum = 0.f;
        #pragma unroll
        for (int e = 0; e < E_; e++) { vals[e] = expf(vals[e] - mx); sum += vals[e]; }
        float inv = 1.f / sum;
        float* o = g_ATTN + ((size_t)b * L_ + l) * E_;
        #pragma unroll
        for (int e = 0; e < E_; e++) o[e] = vals[e] * inv;
    }
}

// ---- K5: node = att_node @ edge + x; write twice
//      grid (B, 4), block 256. Register tile: 13l x 4j per thread, f32x2 FMA.
__global__ void __launch_bounds__(256, 2) k5(float* __restrict__ out) {
    int b = blockIdx.x;
    int dt = blockIdx.y * DT;
    __shared__ float es[E_][DT];            // 25.6 KB
    __shared__ float2 an2[E_][L_ + 2];      // duplicated weights, 40.8 KB
    int t = threadIdx.x;

    for (int idx = t; idx < E_ * (DT / 4); idx += 256) {
        int e = idx >> 5, q = idx & 31;
        ((float4*)es[e])[q] = *(const float4*)(g_EDGE + ((size_t)b * E_ + e) * D_ + dt + q * 4);
    }
    for (int idx = t; idx < L_ * E_; idx += 256) {
        int l = idx / E_, e = idx % E_;
        float v = g_ATTN[(size_t)b * L_ * E_ + idx];
        an2[e][l] = make_float2(v, v);
    }
    __syncthreads();

    int lg = t & 7, jg = t >> 3;
    int j0 = jg * 4;
    unsigned long long acc[13][2];
    #pragma unroll
    for (int k = 0; k < 13; k++) { acc[k][0] = 0ULL; acc[k][1] = 0ULL; }

    for (int e = 0; e < E_; e++) {
        ulonglong2 xv = *(const ulonglong2*)&es[e][j0];
        #pragma unroll
        for (int k = 0; k < 13; k++) {
            int l = lg + 8 * k;
            if (l < L_) {
                unsigned long long aa = *(const unsigned long long*)&an2[e][l];
                acc[k][0] = fma2(aa, xv.x, acc[k][0]);
                acc[k][1] = fma2(aa, xv.y, acc[k][1]);
            }
        }
    }
    #pragma unroll
    for (int k = 0; k < 13; k++) {
        int l = lg + 8 * k;
        if (l < L_) {
            size_t off = ((size_t)b * L_ + l) * D_ + dt + j0;
            float4 x = *(const float4*)(g_X + off);
            float2 lo = *(float2*)&acc[k][0];
            float2 hi = *(float2*)&acc[k][1];
            float4 o = make_float4(lo.x + x.x, lo.y + x.y, hi.x + x.z, hi.y + x.w);
            *(float4*)(out + off) = o;
            *(float4*)(out + BLD + off) = o;
        }
    }
}

extern "C" void kernel_launch(void* const* d_in, const int* in_sizes, int n_in,
                              void* d_out, int out_size) {
    const int*   inputs = (const int*)d_in[0];
    const int*   HT     = (const int*)d_in[1];
    const float* emb1   = (const float*)d_in[4];
    const float* emb2   = (const float*)d_in[5];
    const float* W2     = (const float*)d_in[6];
    const float* W3     = (const float*)d_in[7];
    const float* ctx    = (const float*)d_in[8];
    const float* a      = (const float*)d_in[9];
    const float* a2     = (const float*)d_in[10];
    float* out = (float*)d_out;

    k0<<<4, 512>>>(W2, W3, ctx, a, a2);
    k1<<<B_ * L_, 128>>>(inputs, emb1, emb2, out + 2 * BLD);
    k2<<<B_, 256>>>(HT);
    k3<<<dim3(B_, 4), 256>>>();
    k4<<<B_, 256>>>(HT);
    k5<<<dim3(B_, 4), 256>>>(out);
}

// round 3
// speedup vs baseline: 1.2529x; 1.2408x over previous
#include <cuda_runtime.h>

#define B_ 512
#define L_ 100
#define E_ 50
#define D_ 512
#define DT 128
#define BLD ((size_t)B_ * L_ * D_)
#define NEGF -9000000000000000.0f

typedef unsigned long long ull;

// ---- scratch (static device globals: allocation-free at runtime) ----
__device__ float g_X[(size_t)B_ * L_ * D_];      // gathered node feats (100 MB)
__device__ float g_EDGE[(size_t)B_ * E_ * D_];   // edge feats (50 MB)
__device__ float g_ATTE[(size_t)B_ * E_ * L_];   // att_edge  [B][E][L]
__device__ float g_ATTN[(size_t)B_ * L_ * E_];   // att_node  [B][L][E]
__device__ float g_S[B_ * L_];                   // leaky(c0 + x.w_an)
__device__ float g_U[B_ * L_];                   // x.w_a2n
__device__ float g_wan[D_], g_wa2n[D_], g_w3e[D_];
__device__ float g_c0;

__device__ __forceinline__ float leaky(float x) { return x >= 0.f ? x : 0.2f * x; }

__device__ __forceinline__ ull fma2(ull a, ull b, ull c) {
    ull d;
    asm("fma.rn.f32x2 %0, %1, %2, %3;" : "=l"(d) : "l"(a), "l"(b), "l"(c));
    return d;
}
__device__ __forceinline__ ull dup2(float x) {
    ull d;
    asm("mov.b64 %0, {%1, %1};" : "=l"(d) : "f"(x));
    return d;
}
__device__ __forceinline__ float lo32(ull v) { return ((float2*)&v)->x; }
__device__ __forceinline__ float hi32(ull v) { return ((float2*)&v)->y; }

// ---- K0: fold W2/W3 into vectors
__global__ void k0(const float* __restrict__ W2, const float* __restrict__ W3,
                   const float* __restrict__ ctx, const float* __restrict__ a,
                   const float* __restrict__ a2) {
    int d = threadIdx.x;      // 512
    int which = blockIdx.x;   // 4
    if (which < 3) {
        const float* M = (which == 2) ? W3 : W2;
        const float* vec = (which == 0) ? (a + D_) : (which == 1 ? a2 : (a2 + D_));
        float s = 0.f;
        for (int j = 0; j < D_; j++) s += M[(size_t)d * D_ + j] * vec[j];
        if (which == 0) g_wan[d] = s;
        else if (which == 1) g_wa2n[d] = s;
        else g_w3e[d] = s;
    } else {
        __shared__ float sh[512];
        sh[d] = ctx[d] * a[d];
        __syncthreads();
        for (int o = 256; o > 0; o >>= 1) { if (d < o) sh[d] += sh[d + o]; __syncthreads(); }
        if (d == 0) g_c0 = sh[0];
    }
}

// ---- K1: gather + fused dots
__global__ void k1(const int* __restrict__ inputs, const float* __restrict__ emb1,
                   const float* __restrict__ emb2, float* __restrict__ out3) {
    int bl = blockIdx.x;        // B*L
    int t = threadIdx.x;        // 128
    size_t nid = (size_t)inputs[bl];
    const float4* r1 = (const float4*)(emb1 + nid * D_);
    const float4* r2 = (const float4*)(emb2 + nid * D_);
    float4* xo = (float4*)(g_X + (size_t)bl * D_);
    float4* o3 = (float4*)(out3 + (size_t)bl * D_);

    float4 v = r1[t];
    xo[t] = v;
    o3[t] = r2[t];
    float4 wa = ((const float4*)g_wan)[t];
    float4 wb = ((const float4*)g_wa2n)[t];
    float dan = v.x * wa.x + v.y * wa.y + v.z * wa.z + v.w * wa.w;
    float da2 = v.x * wb.x + v.y * wb.y + v.z * wb.z + v.w * wb.w;

    for (int off = 16; off; off >>= 1) {
        dan += __shfl_xor_sync(0xffffffffu, dan, off);
        da2 += __shfl_xor_sync(0xffffffffu, da2, off);
    }
    __shared__ float sA[4], sB[4];
    if ((t & 31) == 0) { sA[t >> 5] = dan; sB[t >> 5] = da2; }
    __syncthreads();
    if (t == 0) {
        float s = g_c0 + sA[0] + sA[1] + sA[2] + sA[3];
        g_S[bl] = leaky(s);
        g_U[bl] = sB[0] + sB[1] + sB[2] + sB[3];
    }
}

// ---- K2: att_edge[b,e,:] = softmax_l( mask ? s_node[b,l] : NEG )
__global__ void k2(const int* __restrict__ HT) {
    int b = blockIdx.x;
    __shared__ float s[L_];
    int t = threadIdx.x;   // 256
    if (t < L_) s[t] = g_S[b * L_ + t];
    __syncthreads();
    int w = t >> 5, lane = t & 31;
    for (int e = w; e < E_; e += 8) {
        const int* m = HT + ((size_t)b * E_ + e) * L_;
        float vals[4];
        float mx = -3.4e38f;
        #pragma unroll
        for (int k = 0; k < 4; k++) {
            int l = lane + 32 * k;
            float v = -3.4e38f;
            if (l < L_) v = (m[l] > 0) ? s[l] : NEGF;
            vals[k] = v;
            mx = fmaxf(mx, v);
        }
        for (int off = 16; off; off >>= 1) mx = fmaxf(mx, __shfl_xor_sync(0xffffffffu, mx, off));
        float sum = 0.f;
        #pragma unroll
        for (int k = 0; k < 4; k++) {
            int l = lane + 32 * k;
            float ev = 0.f;
            if (l < L_) ev = expf(vals[k] - mx);
            vals[k] = ev;
            sum += ev;
        }
        for (int off = 16; off; off >>= 1) sum += __shfl_xor_sync(0xffffffffu, sum, off);
        float inv = 1.f / sum;
        float* o = g_ATTE + ((size_t)b * E_ + e) * L_;
        #pragma unroll
        for (int k = 0; k < 4; k++) { int l = lane + 32 * k; if (l < L_) o[l] = vals[k] * inv; }
    }
}

// ---- K3: edge[b,e,:] = sum_l att_edge[b,e,l] * x[b,l,:]
//      grid (B,4), block 256. Each thread: 4 e-pairs x 4 j. Weights packed as
//      (w_e0,w_e1) float2 in smem (no duplication); x broadcast via reg pack.
__global__ void __launch_bounds__(256) k3() {
    int b = blockIdx.x;
    int dt = blockIdx.y * DT;
    __shared__ float xs[L_][DT];          // 51.2 KB
    __shared__ float2 awp[L_][28];        // 25 pairs used, pad 28 -> 22.4 KB
    int t = threadIdx.x;

    for (int idx = t; idx < L_ * (DT / 4); idx += 256) {
        int l = idx >> 5, q = idx & 31;
        ((float4*)xs[l])[q] = *(const float4*)(g_X + ((size_t)b * L_ + l) * D_ + dt + q * 4);
    }
    for (int idx = t; idx < E_ * L_; idx += 256) {
        int e = idx / L_, l = idx % L_;
        float v = g_ATTE[(size_t)b * E_ * L_ + idx];
        ((float*)&awp[l][e >> 1])[e & 1] = v;
    }
    __syncthreads();

    int eg = t & 7, jg = t >> 3;
    int j0 = jg * 4;
    ull acc[4][4];  // [pair-slot][j]: lanes = (e0, e1)
    #pragma unroll
    for (int k = 0; k < 4; k++)
        #pragma unroll
        for (int j = 0; j < 4; j++) acc[k][j] = 0ULL;

    #pragma unroll 2
    for (int l = 0; l < L_; l++) {
        float4 xv = *(const float4*)&xs[l][j0];
        ull xx[4] = {dup2(xv.x), dup2(xv.y), dup2(xv.z), dup2(xv.w)};
        #pragma unroll
        for (int k = 0; k < 4; k++) {
            int p = eg + 8 * k;
            if (p < 25) {
                ull w = *(const ull*)&awp[l][p];
                #pragma unroll
                for (int j = 0; j < 4; j++) acc[k][j] = fma2(w, xx[j], acc[k][j]);
            }
        }
    }
    #pragma unroll
    for (int k = 0; k < 4; k++) {
        int p = eg + 8 * k;
        if (p < 25) {
            int e0 = 2 * p;
            float4 o0 = make_float4(lo32(acc[k][0]), lo32(acc[k][1]), lo32(acc[k][2]), lo32(acc[k][3]));
            float4 o1 = make_float4(hi32(acc[k][0]), hi32(acc[k][1]), hi32(acc[k][2]), hi32(acc[k][3]));
            *(float4*)(g_EDGE + ((size_t)b * E_ + e0) * D_ + dt + j0) = o0;
            *(float4*)(g_EDGE + ((size_t)b * E_ + e0 + 1) * D_ + dt + j0) = o1;
        }
    }
}

// ---- K4: v[b,e] = edge.w3e; att_node softmax over e
__global__ void k4(const int* __restrict__ HT) {
    int b = blockIdx.x;
    int t = threadIdx.x;   // 256
    __shared__ float vsh[E_];
    __shared__ float ush[L_];
    __shared__ float4 wsh[D_ / 4];
    int w = t >> 5, lane = t & 31;
    for (int i = t; i < D_ / 4; i += 256) wsh[i] = ((const float4*)g_w3e)[i];
    if (t < L_) ush[t] = g_U[b * L_ + t];
    __syncthreads();
    for (int e = w; e < E_; e += 8) {
        const float4* er = (const float4*)(g_EDGE + ((size_t)b * E_ + e) * D_);
        float d = 0.f;
        #pragma unroll
        for (int i = 0; i < 4; i++) {
            float4 ev = er[lane + 32 * i];
            float4 wv = wsh[lane + 32 * i];
            d += ev.x * wv.x + ev.y * wv.y + ev.z * wv.z + ev.w * wv.w;
        }
        for (int off = 16; off; off >>= 1) d += __shfl_xor_sync(0xffffffffu, d, off);
        if (lane == 0) vsh[e] = d;
    }
    __syncthreads();

    if (t < L_) {
        int l = t;
        float u = ush[l];
        float vals[E_];
        float mx = -3.4e38f;
        #pragma unroll
        for (int e = 0; e < E_; e++) {
            float s2 = leaky(u + vsh[e]);
            float val = (HT[((size_t)b * E_ + e) * L_ + l] > 0) ? s2 : NEGF;
            vals[e] = val;
            mx = fmaxf(mx, val);
        }
        float sum = 0.f;
        #pragma unroll
        for (int e = 0; e < E_; e++) { vals[e] = expf(vals[e] - mx); sum += vals[e]; }
        float inv = 1.f / sum;
        float* o = g_ATTN + ((size_t)b * L_ + l) * E_;
        #pragma unroll
        for (int e = 0; e < E_; e++) o[e] = vals[e] * inv;
    }
}

// ---- K5: node = att_node @ edge + x; write out twice
//      grid (B,4), block 256. Each thread: 7 l-pairs x 4 j.
__global__ void __launch_bounds__(256) k5(float* __restrict__ out) {
    int b = blockIdx.x;
    int dt = blockIdx.y * DT;
    __shared__ float es[E_][DT];          // 25.6 KB
    __shared__ float2 anp[E_][52];        // 50 pairs used, pad 52 -> 20.8 KB
    int t = threadIdx.x;

    for (int idx = t; idx < E_ * (DT / 4); idx += 256) {
        int e = idx >> 5, q = idx & 31;
        ((float4*)es[e])[q] = *(const float4*)(g_EDGE + ((size_t)b * E_ + e) * D_ + dt + q * 4);
    }
    for (int idx = t; idx < L_ * E_; idx += 256) {
        int l = idx / E_, e = idx % E_;
        float v = g_ATTN[(size_t)b * L_ * E_ + idx];
        ((float*)&anp[e][l >> 1])[l & 1] = v;
    }
    __syncthreads();

    int lg = t & 7, jg = t >> 3;
    int j0 = jg * 4;
    ull acc[7][4];  // [pair-slot][j]: lanes = (l0, l1)
    #pragma unroll
    for (int k = 0; k < 7; k++)
        #pragma unroll
        for (int j = 0; j < 4; j++) acc[k][j] = 0ULL;

    #pragma unroll 2
    for (int e = 0; e < E_; e++) {
        float4 xv = *(const float4*)&es[e][j0];
        ull xx[4] = {dup2(xv.x), dup2(xv.y), dup2(xv.z), dup2(xv.w)};
        #pragma unroll
        for (int k = 0; k < 7; k++) {
            int p = lg + 8 * k;
            if (p < 50) {
                ull w = *(const ull*)&anp[e][p];
                #pragma unroll
                for (int j = 0; j < 4; j++) acc[k][j] = fma2(w, xx[j], acc[k][j]);
            }
        }
    }
    #pragma unroll
    for (int k = 0; k < 7; k++) {
        int p = lg + 8 * k;
        if (p < 50) {
            int l0 = 2 * p;
            size_t off0 = ((size_t)b * L_ + l0) * D_ + dt + j0;
            size_t off1 = off0 + D_;
            float4 x0 = *(const float4*)(g_X + off0);
            float4 x1 = *(const float4*)(g_X + off1);
            float4 o0 = make_float4(lo32(acc[k][0]) + x0.x, lo32(acc[k][1]) + x0.y,
                                    lo32(acc[k][2]) + x0.z, lo32(acc[k][3]) + x0.w);
            float4 o1 = make_float4(hi32(acc[k][0]) + x1.x, hi32(acc[k][1]) + x1.y,
                                    hi32(acc[k][2]) + x1.z, hi32(acc[k][3]) + x1.w);
            *(float4*)(out + off0) = o0;
            *(float4*)(out + BLD + off0) = o0;
            *(float4*)(out + off1) = o1;
            *(float4*)(out + BLD + off1) = o1;
        }
    }
}

extern "C" void kernel_launch(void* const* d_in, const int* in_sizes, int n_in,
                              void* d_out, int out_size) {
    const int*   inputs = (const int*)d_in[0];
    const int*   HT     = (const int*)d_in[1];
    const float* emb1   = (const float*)d_in[4];
    const float* emb2   = (const float*)d_in[5];
    const float* W2     = (const float*)d_in[6];
    const float* W3     = (const float*)d_in[7];
    const float* ctx    = (const float*)d_in[8];
    const float* a      = (const float*)d_in[9];
    const float* a2     = (const float*)d_in[10];
    float* out = (float*)d_out;

    k0<<<4, 512>>>(W2, W3, ctx, a, a2);
    k1<<<B_ * L_, 128>>>(inputs, emb1, emb2, out + 2 * BLD);
    k2<<<B_, 256>>>(HT);
    k3<<<dim3(B_, 4), 256>>>();
    k4<<<B_, 256>>>(HT);
    k5<<<dim3(B_, 4), 256>>>(out);
}

// round 4
// speedup vs baseline: 1.4809x; 1.1819x over previous
#include <cuda_runtime.h>

#define B_ 512
#define L_ 100
#define E_ 50
#define D_ 512
#define DT 128
#define BLD ((size_t)B_ * L_ * D_)
#define NEGF -9000000000000000.0f

typedef unsigned long long ull;

// ---- scratch (static device globals: allocation-free at runtime) ----
__device__ float g_X[(size_t)B_ * L_ * D_];        // gathered node feats (100 MB)
__device__ float g_EDGE[(size_t)B_ * E_ * D_];     // edge feats (50 MB)
__device__ float2 g_ATTEP[(size_t)B_ * L_ * 28];   // att_edge, e-pair packed [b][l][pair]
__device__ float2 g_ATTNP[(size_t)B_ * E_ * 52];   // att_node, l-pair packed [b][e][pair]
__device__ float g_S[B_ * L_];                     // leaky(c0 + x.w_an)
__device__ float g_U[B_ * L_];                     // x.w_a2n
__device__ float g_wan[D_], g_wa2n[D_], g_w3e[D_];
__device__ float g_c0;

__device__ __forceinline__ float leaky(float x) { return x >= 0.f ? x : 0.2f * x; }

__device__ __forceinline__ ull fma2(ull a, ull b, ull c) {
    ull d;
    asm("fma.rn.f32x2 %0, %1, %2, %3;" : "=l"(d) : "l"(a), "l"(b), "l"(c));
    return d;
}
__device__ __forceinline__ ull dup2(float x) {
    ull d;
    asm("mov.b64 %0, {%1, %1};" : "=l"(d) : "f"(x));
    return d;
}
__device__ __forceinline__ float lo32(ull v) { return ((float2*)&v)->x; }
__device__ __forceinline__ float hi32(ull v) { return ((float2*)&v)->y; }

// ---- K0: fold W2/W3 into vectors
__global__ void k0(const float* __restrict__ W2, const float* __restrict__ W3,
                   const float* __restrict__ ctx, const float* __restrict__ a,
                   const float* __restrict__ a2) {
    int d = threadIdx.x;      // 512
    int which = blockIdx.x;   // 4
    if (which < 3) {
        const float* M = (which == 2) ? W3 : W2;
        const float* vec = (which == 0) ? (a + D_) : (which == 1 ? a2 : (a2 + D_));
        float s = 0.f;
        for (int j = 0; j < D_; j++) s += M[(size_t)d * D_ + j] * vec[j];
        if (which == 0) g_wan[d] = s;
        else if (which == 1) g_wa2n[d] = s;
        else g_w3e[d] = s;
    } else {
        __shared__ float sh[512];
        sh[d] = ctx[d] * a[d];
        __syncthreads();
        for (int o = 256; o > 0; o >>= 1) { if (d < o) sh[d] += sh[d + o]; __syncthreads(); }
        if (d == 0) g_c0 = sh[0];
    }
}

// ---- K1: gather + fused dots
__global__ void k1(const int* __restrict__ inputs, const float* __restrict__ emb1,
                   const float* __restrict__ emb2, float* __restrict__ out3) {
    int bl = blockIdx.x;        // B*L
    int t = threadIdx.x;        // 128
    size_t nid = (size_t)inputs[bl];
    const float4* r1 = (const float4*)(emb1 + nid * D_);
    const float4* r2 = (const float4*)(emb2 + nid * D_);
    float4* xo = (float4*)(g_X + (size_t)bl * D_);
    float4* o3 = (float4*)(out3 + (size_t)bl * D_);

    float4 v = r1[t];
    xo[t] = v;
    o3[t] = r2[t];
    float4 wa = ((const float4*)g_wan)[t];
    float4 wb = ((const float4*)g_wa2n)[t];
    float dan = v.x * wa.x + v.y * wa.y + v.z * wa.z + v.w * wa.w;
    float da2 = v.x * wb.x + v.y * wb.y + v.z * wb.z + v.w * wb.w;

    for (int off = 16; off; off >>= 1) {
        dan += __shfl_xor_sync(0xffffffffu, dan, off);
        da2 += __shfl_xor_sync(0xffffffffu, da2, off);
    }
    __shared__ float sA[4], sB[4];
    if ((t & 31) == 0) { sA[t >> 5] = dan; sB[t >> 5] = da2; }
    __syncthreads();
    if (t == 0) {
        float s = g_c0 + sA[0] + sA[1] + sA[2] + sA[3];
        g_S[bl] = leaky(s);
        g_U[bl] = sB[0] + sB[1] + sB[2] + sB[3];
    }
}

// ---- K2: att_edge softmax over l, written e-pair-packed: ATTEP[b][l][e>>1].{x,y}
__global__ void k2(const int* __restrict__ HT) {
    int b = blockIdx.x;
    __shared__ float s[L_];
    int t = threadIdx.x;   // 256
    if (t < L_) s[t] = g_S[b * L_ + t];
    // zero-fill pad pairs 25..27 for all l
    for (int idx = t; idx < L_ * 3; idx += 256) {
        int l = idx / 3, p = 25 + idx % 3;
        g_ATTEP[(size_t)b * L_ * 28 + l * 28 + p] = make_float2(0.f, 0.f);
    }
    __syncthreads();
    float* op = (float*)(g_ATTEP + (size_t)b * L_ * 28);
    int w = t >> 5, lane = t & 31;
    for (int e = w; e < E_; e += 8) {
        const int* m = HT + ((size_t)b * E_ + e) * L_;
        float vals[4];
        float mx = -3.4e38f;
        #pragma unroll
        for (int k = 0; k < 4; k++) {
            int l = lane + 32 * k;
            float v = -3.4e38f;
            if (l < L_) v = (m[l] > 0) ? s[l] : NEGF;
            vals[k] = v;
            mx = fmaxf(mx, v);
        }
        for (int off = 16; off; off >>= 1) mx = fmaxf(mx, __shfl_xor_sync(0xffffffffu, mx, off));
        float sum = 0.f;
        #pragma unroll
        for (int k = 0; k < 4; k++) {
            int l = lane + 32 * k;
            float ev = 0.f;
            if (l < L_) ev = expf(vals[k] - mx);
            vals[k] = ev;
            sum += ev;
        }
        for (int off = 16; off; off >>= 1) sum += __shfl_xor_sync(0xffffffffu, sum, off);
        float inv = 1.f / sum;
        #pragma unroll
        for (int k = 0; k < 4; k++) {
            int l = lane + 32 * k;
            if (l < L_) op[(l * 28 + (e >> 1)) * 2 + (e & 1)] = vals[k] * inv;
        }
    }
}

// ---- K3: edge[b,e,:] = sum_l attE[b,e,l] * x[b,l,:]
//      grid (B,4), block 448 = 14 warps x 2 e-pairs (28 pairs exact, E padded 56).
__global__ void __launch_bounds__(448, 3) k3() {
    int b = blockIdx.x;
    int dt = blockIdx.y * DT;
    __shared__ float xs[L_][DT];          // 51.2 KB
    __shared__ float2 awp[L_][28];        // 22.4 KB
    int t = threadIdx.x;

    for (int idx = t; idx < L_ * (DT / 4); idx += 448) {
        int l = idx >> 5, q = idx & 31;
        ((float4*)xs[l])[q] = *(const float4*)(g_X + ((size_t)b * L_ + l) * D_ + dt + q * 4);
    }
    {
        const float4* src = (const float4*)(g_ATTEP + (size_t)b * L_ * 28);
        float4* dst = (float4*)&awp[0][0];
        for (int idx = t; idx < L_ * 28 / 2; idx += 448) dst[idx] = src[idx];
    }
    __syncthreads();

    int lane = t & 31, w = t >> 5;   // w 0..13
    int j0 = lane * 4;
    int p0 = 2 * w;                  // pairs p0, p0+1
    ull acc[2][4];
    #pragma unroll
    for (int k = 0; k < 2; k++)
        #pragma unroll
        for (int j = 0; j < 4; j++) acc[k][j] = 0ULL;

    #pragma unroll 2
    for (int l = 0; l < L_; l++) {
        float4 xv = *(const float4*)&xs[l][j0];
        ull xx[4] = {dup2(xv.x), dup2(xv.y), dup2(xv.z), dup2(xv.w)};
        ulonglong2 wp = *(const ulonglong2*)&awp[l][p0];
        #pragma unroll
        for (int j = 0; j < 4; j++) {
            acc[0][j] = fma2(wp.x, xx[j], acc[0][j]);
            acc[1][j] = fma2(wp.y, xx[j], acc[1][j]);
        }
    }
    #pragma unroll
    for (int k = 0; k < 2; k++) {
        int p = p0 + k;
        if (p < 25) {
            int e0 = 2 * p;
            float4 o0 = make_float4(lo32(acc[k][0]), lo32(acc[k][1]), lo32(acc[k][2]), lo32(acc[k][3]));
            float4 o1 = make_float4(hi32(acc[k][0]), hi32(acc[k][1]), hi32(acc[k][2]), hi32(acc[k][3]));
            *(float4*)(g_EDGE + ((size_t)b * E_ + e0) * D_ + dt + j0) = o0;
            *(float4*)(g_EDGE + ((size_t)b * E_ + e0 + 1) * D_ + dt + j0) = o1;
        }
    }
}

// ---- K4: v[b,e] = edge.w3e; att_node softmax over e, written l-pair-packed
__global__ void k4(const int* __restrict__ HT) {
    int b = blockIdx.x;
    int t = threadIdx.x;   // 256
    __shared__ float vsh[E_];
    __shared__ float ush[L_];
    __shared__ float4 wsh[D_ / 4];
    int w = t >> 5, lane = t & 31;
    for (int i = t; i < D_ / 4; i += 256) wsh[i] = ((const float4*)g_w3e)[i];
    if (t < L_) ush[t] = g_U[b * L_ + t];
    // zero-fill pad pairs 50,51 for all e
    for (int idx = t; idx < E_ * 2; idx += 256) {
        int e = idx >> 1, p = 50 + (idx & 1);
        g_ATTNP[(size_t)b * E_ * 52 + e * 52 + p] = make_float2(0.f, 0.f);
    }
    __syncthreads();
    for (int e = w; e < E_; e += 8) {
        const float4* er = (const float4*)(g_EDGE + ((size_t)b * E_ + e) * D_);
        float d = 0.f;
        #pragma unroll
        for (int i = 0; i < 4; i++) {
            float4 ev = er[lane + 32 * i];
            float4 wv = wsh[lane + 32 * i];
            d += ev.x * wv.x + ev.y * wv.y + ev.z * wv.z + ev.w * wv.w;
        }
        for (int off = 16; off; off >>= 1) d += __shfl_xor_sync(0xffffffffu, d, off);
        if (lane == 0) vsh[e] = d;
    }
    __syncthreads();

    if (t < L_) {
        int l = t;
        float u = ush[l];
        float vals[E_];
        float mx = -3.4e38f;
        #pragma unroll
        for (int e = 0; e < E_; e++) {
            float s2 = leaky(u + vsh[e]);
            float val = (HT[((size_t)b * E_ + e) * L_ + l] > 0) ? s2 : NEGF;
            vals[e] = val;
            mx = fmaxf(mx, val);
        }
        float sum = 0.f;
        #pragma unroll
        for (int e = 0; e < E_; e++) { vals[e] = expf(vals[e] - mx); sum += vals[e]; }
        float inv = 1.f / sum;
        float* op = (float*)(g_ATTNP + (size_t)b * E_ * 52);
        #pragma unroll
        for (int e = 0; e < E_; e++) op[(e * 52 + (l >> 1)) * 2 + (l & 1)] = vals[e] * inv;
    }
}

// ---- K5: node = att_node @ edge + x; write out twice.
//      grid (B,4), block 416 = 13 warps x 4 l-pairs (52 pairs exact, L padded 104).
__global__ void __launch_bounds__(416, 2) k5(float* __restrict__ out) {
    int b = blockIdx.x;
    int dt = blockIdx.y * DT;
    __shared__ float es[E_][DT];          // 25.6 KB
    __shared__ float2 anp[E_][52];        // 20.8 KB
    int t = threadIdx.x;

    for (int idx = t; idx < E_ * (DT / 4); idx += 416) {
        int e = idx >> 5, q = idx & 31;
        ((float4*)es[e])[q] = *(const float4*)(g_EDGE + ((size_t)b * E_ + e) * D_ + dt + q * 4);
    }
    {
        const float4* src = (const float4*)(g_ATTNP + (size_t)b * E_ * 52);
        float4* dst = (float4*)&anp[0][0];
        for (int idx = t; idx < E_ * 52 / 2; idx += 416) dst[idx] = src[idx];
    }
    __syncthreads();

    int lane = t & 31, w = t >> 5;   // w 0..12
    int j0 = lane * 4;
    int p0 = 4 * w;                  // pairs p0..p0+3
    ull acc[4][4];
    #pragma unroll
    for (int k = 0; k < 4; k++)
        #pragma unroll
        for (int j = 0; j < 4; j++) acc[k][j] = 0ULL;

    #pragma unroll 2
    for (int e = 0; e < E_; e++) {
        float4 xv = *(const float4*)&es[e][j0];
        ull xx[4] = {dup2(xv.x), dup2(xv.y), dup2(xv.z), dup2(xv.w)};
        ulonglong2 wa = *(const ulonglong2*)&anp[e][p0];
        ulonglong2 wb = *(const ulonglong2*)&anp[e][p0 + 2];
        #pragma unroll
        for (int j = 0; j < 4; j++) {
            acc[0][j] = fma2(wa.x, xx[j], acc[0][j]);
            acc[1][j] = fma2(wa.y, xx[j], acc[1][j]);
            acc[2][j] = fma2(wb.x, xx[j], acc[2][j]);
            acc[3][j] = fma2(wb.y, xx[j], acc[3][j]);
        }
    }
    #pragma unroll
    for (int k = 0; k < 4; k++) {
        int p = p0 + k;
        if (p < 50) {
            int l0 = 2 * p;
            size_t off0 = ((size_t)b * L_ + l0) * D_ + dt + j0;
            size_t off1 = off0 + D_;
            float4 x0 = *(const float4*)(g_X + off0);
            float4 x1 = *(const float4*)(g_X + off1);
            float4 o0 = make_float4(lo32(acc[k][0]) + x0.x, lo32(acc[k][1]) + x0.y,
                                    lo32(acc[k][2]) + x0.z, lo32(acc[k][3]) + x0.w);
            float4 o1 = make_float4(hi32(acc[k][0]) + x1.x, hi32(acc[k][1]) + x1.y,
                                    hi32(acc[k][2]) + x1.z, hi32(acc[k][3]) + x1.w);
            *(float4*)(out + off0) = o0;
            *(float4*)(out + BLD + off0) = o0;
            *(float4*)(out + off1) = o1;
            *(float4*)(out + BLD + off1) = o1;
        }
    }
}

extern "C" void kernel_launch(void* const* d_in, const int* in_sizes, int n_in,
                              void* d_out, int out_size) {
    const int*   inputs = (const int*)d_in[0];
    const int*   HT     = (const int*)d_in[1];
    const float* emb1   = (const float*)d_in[4];
    const float* emb2   = (const float*)d_in[5];
    const float* W2     = (const float*)d_in[6];
    const float* W3     = (const float*)d_in[7];
    const float* ctx    = (const float*)d_in[8];
    const float* a      = (const float*)d_in[9];
    const float* a2     = (const float*)d_in[10];
    float* out = (float*)d_out;

    k0<<<4, 512>>>(W2, W3, ctx, a, a2);
    k1<<<B_ * L_, 128>>>(inputs, emb1, emb2, out + 2 * BLD);
    k2<<<B_, 256>>>(HT);
    k3<<<dim3(B_, 4), 448>>>();
    k4<<<B_, 256>>>(HT);
    k5<<<dim3(B_, 4), 416>>>(out);
}